// round 1
// baseline (speedup 1.0000x reference)
#include <cuda_runtime.h>

#define N_NODES 50000
#define IN_DIM  7688
#define HID     200
#define OUT_DIM 8
#define N_EDGES 1600000

// ---------------- scratch (device globals; no allocation allowed) -------------
__device__ float g_deg[N_NODES];                    // deg, then dis = deg^-1/2 (in place)
__device__ float g_norm[N_EDGES];
__device__ float g_H1[(size_t)N_NODES * HID];       // x @ W1
__device__ float g_out1[(size_t)N_NODES * HID];     // propagated layer-1 (then relu'd h)
__device__ float g_H2[(size_t)N_NODES * OUT_DIM];   // h @ W2
__device__ int   g_is64;

// ---------------- helpers ----------------------------------------------------
__device__ __forceinline__ int edge_at(const void* ei, size_t pos, int is64) {
    if (is64) return (int)((const long long*)ei)[pos];
    return ((const int*)ei)[pos];
}

__device__ __forceinline__ unsigned f2tf(float f) {
    unsigned r;
    asm volatile("cvt.rna.tf32.f32 %0, %1;" : "=r"(r) : "f"(f));
    return r;
}

#define MMA_TF32(c, a, b)                                                     \
    asm volatile(                                                             \
        "mma.sync.aligned.m16n8k8.row.col.f32.tf32.tf32.f32 "                 \
        "{%0,%1,%2,%3}, {%4,%5,%6,%7}, {%8,%9}, {%0,%1,%2,%3};\n"             \
        : "+f"((c)[0]), "+f"((c)[1]), "+f"((c)[2]), "+f"((c)[3])              \
        : "r"((a)[0]), "r"((a)[1]), "r"((a)[2]), "r"((a)[3]),                 \
          "r"((b)[0]), "r"((b)[1]))

// ---------------- dtype detection (int64 vs int32 edge_index) ----------------
__global__ void detect_kernel(const unsigned* __restrict__ w, int n_check) {
    __shared__ int bad;
    if (threadIdx.x == 0) bad = 0;
    __syncthreads();
    int local = 0;
    for (int i = threadIdx.x; i < n_check; i += blockDim.x)
        if (w[2 * i + 1] != 0u) local = 1;
    if (local) bad = 1;
    __syncthreads();
    if (threadIdx.x == 0) g_is64 = bad ? 0 : 1;  // all-odd-words-zero => int64
}

// ---------------- degree / norm ----------------------------------------------
__global__ void init_deg_kernel() {
    int i = blockIdx.x * blockDim.x + threadIdx.x;
    if (i < N_NODES) g_deg[i] = 1.0f;  // self-loop weight 1
}

__global__ void accum_deg_kernel(const void* __restrict__ ei,
                                 const float* __restrict__ ew) {
    int e = blockIdx.x * blockDim.x + threadIdx.x;
    if (e >= N_EDGES) return;
    int is64 = g_is64;
    int d = edge_at(ei, (size_t)N_EDGES + e, is64);
    atomicAdd(&g_deg[d], ew[e]);
}

__global__ void rsqrt_kernel() {
    int i = blockIdx.x * blockDim.x + threadIdx.x;
    if (i < N_NODES) {
        float dg = g_deg[i];
        g_deg[i] = (dg > 0.0f) ? rsqrtf(dg) : 0.0f;
    }
}

__global__ void norm_kernel(const void* __restrict__ ei,
                            const float* __restrict__ ew) {
    int e = blockIdx.x * blockDim.x + threadIdx.x;
    if (e >= N_EDGES) return;
    int is64 = g_is64;
    int s = edge_at(ei, e, is64);
    int d = edge_at(ei, (size_t)N_EDGES + e, is64);
    g_norm[e] = g_deg[s] * ew[e] * g_deg[d];
}

// ---------------- GEMM1: H1 = X @ W1 (tf32 tensor cores) ---------------------
// Block tile: 128(M) x 200(N=all) x 16(K). 320 threads = 10 warps in 2(m)x5(n),
// warp tile 64x40 = 4x5 mma tiles of m16n8k8.
#define BM 128
#define BK 16
#define GT 320
#define ASTR 20  // A smem row stride (conflict-free for frag loads)

__global__ __launch_bounds__(GT)
void gemm1_kernel(const float* __restrict__ X, const float* __restrict__ W1) {
    __shared__ unsigned As[BM * ASTR];   // [m][k]
    __shared__ unsigned Bs[BK * HID];    // [k][n]

    const int tid  = threadIdx.x;
    const int lane = tid & 31;
    const int warp = tid >> 5;
    const int gid  = lane >> 2;   // 0..7
    const int tig  = lane & 3;    // 0..3
    const int wm   = warp / 5;    // 0..1
    const int wn   = warp % 5;    // 0..4
    const int m0   = blockIdx.x * BM;

    float c[4][5][4];
#pragma unroll
    for (int mi = 0; mi < 4; mi++)
#pragma unroll
        for (int ni = 0; ni < 5; ni++)
#pragma unroll
            for (int r = 0; r < 4; r++) c[mi][ni][r] = 0.0f;

    for (int k0 = 0; k0 < IN_DIM; k0 += BK) {
        // load A tile (128x16) as tf32
        for (int i = tid; i < (BM * BK) / 4; i += GT) {
            int m  = i >> 2;
            int kq = (i & 3) << 2;
            int gm = m0 + m;
            int gk = k0 + kq;
            float4 v = make_float4(0.f, 0.f, 0.f, 0.f);
            if (gm < N_NODES && gk < IN_DIM)
                v = *reinterpret_cast<const float4*>(X + (size_t)gm * IN_DIM + gk);
            unsigned* p = &As[m * ASTR + kq];
            p[0] = f2tf(v.x); p[1] = f2tf(v.y); p[2] = f2tf(v.z); p[3] = f2tf(v.w);
        }
        // load B tile (16x200) as tf32
        for (int i = tid; i < (BK * HID) / 4; i += GT) {
            int kk = i / 50;
            int nq = (i % 50) << 2;
            int gk = k0 + kk;
            float4 v = make_float4(0.f, 0.f, 0.f, 0.f);
            if (gk < IN_DIM)
                v = *reinterpret_cast<const float4*>(W1 + (size_t)gk * HID + nq);
            unsigned* p = &Bs[kk * HID + nq];
            p[0] = f2tf(v.x); p[1] = f2tf(v.y); p[2] = f2tf(v.z); p[3] = f2tf(v.w);
        }
        __syncthreads();

#pragma unroll
        for (int kk = 0; kk < BK; kk += 8) {
            unsigned a[4][4], b[5][2];
#pragma unroll
            for (int mi = 0; mi < 4; mi++) {
                int mr = wm * 64 + mi * 16 + gid;
                a[mi][0] = As[mr * ASTR + kk + tig];
                a[mi][1] = As[(mr + 8) * ASTR + kk + tig];
                a[mi][2] = As[mr * ASTR + kk + tig + 4];
                a[mi][3] = As[(mr + 8) * ASTR + kk + tig + 4];
            }
#pragma unroll
            for (int ni = 0; ni < 5; ni++) {
                int nc = wn * 40 + ni * 8 + gid;
                b[ni][0] = Bs[(kk + tig) * HID + nc];
                b[ni][1] = Bs[(kk + tig + 4) * HID + nc];
            }
#pragma unroll
            for (int mi = 0; mi < 4; mi++)
#pragma unroll
                for (int ni = 0; ni < 5; ni++) MMA_TF32(c[mi][ni], a[mi], b[ni]);
        }
        __syncthreads();
    }

    // epilogue: write H1 and initialize out1 with self-loop contribution
#pragma unroll
    for (int mi = 0; mi < 4; mi++) {
        int r0 = m0 + wm * 64 + mi * 16 + gid;
        int r1 = r0 + 8;
        float s0 = 0.f, s1 = 0.f;
        if (r0 < N_NODES) { float dv = g_deg[r0]; s0 = dv * dv; }
        if (r1 < N_NODES) { float dv = g_deg[r1]; s1 = dv * dv; }
#pragma unroll
        for (int ni = 0; ni < 5; ni++) {
            int col = wn * 40 + ni * 8 + 2 * tig;
            if (r0 < N_NODES) {
                size_t o = (size_t)r0 * HID + col;
                g_H1[o]     = c[mi][ni][0];
                g_H1[o + 1] = c[mi][ni][1];
                g_out1[o]     = c[mi][ni][0] * s0;
                g_out1[o + 1] = c[mi][ni][1] * s0;
            }
            if (r1 < N_NODES) {
                size_t o = (size_t)r1 * HID + col;
                g_H1[o]     = c[mi][ni][2];
                g_H1[o + 1] = c[mi][ni][3];
                g_out1[o]     = c[mi][ni][2] * s1;
                g_out1[o + 1] = c[mi][ni][3] * s1;
            }
        }
    }
}

// ---------------- propagation 1 (one warp per edge) --------------------------
__global__ void scatter1_kernel(const void* __restrict__ ei) {
    int e = blockIdx.x * 8 + (threadIdx.x >> 5);
    if (e >= N_EDGES) return;
    int lane = threadIdx.x & 31;
    int is64 = g_is64;
    int s = edge_at(ei, e, is64);
    int d = edge_at(ei, (size_t)N_EDGES + e, is64);
    float w = g_norm[e];
    const float4* hrow = (const float4*)(g_H1 + (size_t)s * HID);
    float* orow = g_out1 + (size_t)d * HID;
    for (int q = lane; q < HID / 4; q += 32) {
        float4 v = hrow[q];
        atomicAdd(orow + q * 4 + 0, v.x * w);
        atomicAdd(orow + q * 4 + 1, v.y * w);
        atomicAdd(orow + q * 4 + 2, v.z * w);
        atomicAdd(orow + q * 4 + 3, v.w * w);
    }
}

// ---------------- bias + relu ------------------------------------------------
__global__ void relu_kernel(const float* __restrict__ b1) {
    size_t idx = (size_t)blockIdx.x * blockDim.x + threadIdx.x;
    if (idx >= (size_t)N_NODES * HID) return;
    int col = (int)(idx % HID);
    float v = g_out1[idx] + b1[col];
    g_out1[idx] = v > 0.f ? v : 0.f;
}

// ---------------- GEMM2: H2 = h @ W2, and init d_out with self-loop ----------
__global__ void gemm2_kernel(const float* __restrict__ W2,
                             const float* __restrict__ b2,
                             float* __restrict__ outp) {
    __shared__ float W2s[HID * OUT_DIM];
    int tid = threadIdx.x;
    for (int i = tid; i < HID * OUT_DIM; i += blockDim.x) W2s[i] = W2[i];
    __syncthreads();
    int row = blockIdx.x * blockDim.x + tid;
    if (row >= N_NODES) return;
    float acc[OUT_DIM];
#pragma unroll
    for (int o = 0; o < OUT_DIM; o++) acc[o] = 0.f;
    const float* hr = g_out1 + (size_t)row * HID;
#pragma unroll 4
    for (int k = 0; k < HID; k++) {
        float hv = hr[k];
#pragma unroll
        for (int o = 0; o < OUT_DIM; o++) acc[o] += hv * W2s[k * OUT_DIM + o];
    }
    float dv = g_deg[row];
    float s  = dv * dv;
#pragma unroll
    for (int o = 0; o < OUT_DIM; o++) {
        g_H2[(size_t)row * OUT_DIM + o] = acc[o];
        outp[(size_t)row * OUT_DIM + o] = acc[o] * s + b2[o];
    }
}

// ---------------- propagation 2 (8 threads per edge) -------------------------
__global__ void scatter2_kernel(const void* __restrict__ ei,
                                float* __restrict__ outp) {
    long long idx = (long long)blockIdx.x * blockDim.x + threadIdx.x;
    int e = (int)(idx >> 3);
    if (e >= N_EDGES) return;
    int f = (int)(idx & 7);
    int is64 = g_is64;
    int s = edge_at(ei, e, is64);
    int d = edge_at(ei, (size_t)N_EDGES + e, is64);
    float w = g_norm[e];
    atomicAdd(outp + (size_t)d * OUT_DIM + f, g_H2[(size_t)s * OUT_DIM + f] * w);
}

// ---------------- launch -----------------------------------------------------
extern "C" void kernel_launch(void* const* d_in, const int* in_sizes, int n_in,
                              void* d_out, int out_size) {
    const float* x  = (const float*)d_in[0];
    const float* ew = (const float*)d_in[1];
    const float* W1 = (const float*)d_in[2];
    const float* b1 = (const float*)d_in[3];
    const float* W2 = (const float*)d_in[4];
    const float* b2 = (const float*)d_in[5];
    const void*  ei = d_in[6];
    float* outp = (float*)d_out;

    detect_kernel<<<1, 256>>>((const unsigned*)ei, 262144);
    init_deg_kernel<<<(N_NODES + 255) / 256, 256>>>();
    accum_deg_kernel<<<(N_EDGES + 255) / 256, 256>>>(ei, ew);
    rsqrt_kernel<<<(N_NODES + 255) / 256, 256>>>();
    norm_kernel<<<(N_EDGES + 255) / 256, 256>>>(ei, ew);
    gemm1_kernel<<<(N_NODES + BM - 1) / BM, GT>>>(x, W1);
    scatter1_kernel<<<(N_EDGES + 7) / 8, 256>>>(ei);
    relu_kernel<<<(int)(((size_t)N_NODES * HID + 255) / 256), 256>>>(b1);
    gemm2_kernel<<<(N_NODES + 255) / 256, 256>>>(W2, b2, outp);
    scatter2_kernel<<<(int)(((long long)N_EDGES * 8 + 255) / 256), 256>>>(ei, outp);
}

// round 2
// speedup vs baseline: 2.2508x; 2.2508x over previous
#include <cuda_runtime.h>

#define N_NODES 50000
#define IN_DIM  7688
#define HID     200
#define OUT_DIM 8
#define N_EDGES 1600000

// ---------------- scratch (device globals; no allocation allowed) -------------
__device__ float g_dis[N_NODES];                    // deg, then deg^-1/2 in place
__device__ int   g_cnt[N_NODES];
__device__ int   g_off[N_NODES + 1];
__device__ int   g_cur[N_NODES];
__device__ int   g_csr_src[N_EDGES];
__device__ float g_csr_w[N_EDGES];
__device__ float g_H1[(size_t)N_NODES * HID];       // x @ W1
__device__ float g_h[(size_t)N_NODES * HID];        // relu(prop1 + b1)
__device__ float g_H2[(size_t)N_NODES * OUT_DIM];   // h @ W2
__device__ int   g_is64;

// ---------------- helpers ----------------------------------------------------
__device__ __forceinline__ int edge_at(const void* ei, size_t pos, int is64) {
    if (is64) return (int)((const long long*)ei)[pos];
    return ((const int*)ei)[pos];
}

__device__ __forceinline__ unsigned f2tf(float f) {
    unsigned r;
    asm volatile("cvt.rna.tf32.f32 %0, %1;" : "=r"(r) : "f"(f));
    return r;
}

__device__ __forceinline__ void cp16(unsigned saddr, const void* g, int sz) {
    asm volatile("cp.async.cg.shared.global [%0], [%1], 16, %2;\n"
                 :: "r"(saddr), "l"(g), "r"(sz));
}

#define MMA_TF32(c, a, b)                                                     \
    asm volatile(                                                             \
        "mma.sync.aligned.m16n8k8.row.col.f32.tf32.tf32.f32 "                 \
        "{%0,%1,%2,%3}, {%4,%5,%6,%7}, {%8,%9}, {%0,%1,%2,%3};\n"             \
        : "+f"((c)[0]), "+f"((c)[1]), "+f"((c)[2]), "+f"((c)[3])              \
        : "r"((a)[0]), "r"((a)[1]), "r"((a)[2]), "r"((a)[3]),                 \
          "r"((b)[0]), "r"((b)[1]))

// ---------------- dtype detection (int64 vs int32 edge_index) ----------------
__global__ void detect_kernel(const unsigned* __restrict__ w, int n_check) {
    __shared__ int bad;
    if (threadIdx.x == 0) bad = 0;
    __syncthreads();
    int local = 0;
    for (int i = threadIdx.x; i < n_check; i += blockDim.x)
        if (w[2 * i + 1] != 0u) local = 1;
    if (local) bad = 1;
    __syncthreads();
    if (threadIdx.x == 0) g_is64 = bad ? 0 : 1;  // all-odd-words-zero => int64
}

// ---------------- degree + histogram -----------------------------------------
__global__ void init_kernel() {
    int i = blockIdx.x * blockDim.x + threadIdx.x;
    if (i < N_NODES) { g_dis[i] = 1.0f; g_cnt[i] = 0; }  // self-loop weight 1
}

__global__ void accum_kernel(const void* __restrict__ ei,
                             const float* __restrict__ ew) {
    int e = blockIdx.x * blockDim.x + threadIdx.x;
    if (e >= N_EDGES) return;
    int is64 = g_is64;
    int d = edge_at(ei, (size_t)N_EDGES + e, is64);
    atomicAdd(&g_dis[d], ew[e]);
    atomicAdd(&g_cnt[d], 1);
}

__global__ void rsqrt_kernel() {
    int i = blockIdx.x * blockDim.x + threadIdx.x;
    if (i < N_NODES) {
        float dg = g_dis[i];
        g_dis[i] = (dg > 0.0f) ? rsqrtf(dg) : 0.0f;
    }
}

// ---------------- exclusive scan over g_cnt (single block) -------------------
__global__ void scan_kernel() {
    __shared__ int part[1024];
    const int tid = threadIdx.x;
    const int CH = (N_NODES + 1023) / 1024;  // 49
    int base = tid * CH;
    int s = 0;
    for (int i = 0; i < CH; i++) {
        int idx = base + i;
        if (idx < N_NODES) s += g_cnt[idx];
    }
    part[tid] = s;
    __syncthreads();
    for (int off = 1; off < 1024; off <<= 1) {
        int v = (tid >= off) ? part[tid - off] : 0;
        __syncthreads();
        part[tid] += v;
        __syncthreads();
    }
    int ex = part[tid] - s;
    for (int i = 0; i < CH; i++) {
        int idx = base + i;
        if (idx < N_NODES) {
            g_off[idx] = ex;
            g_cur[idx] = ex;
            ex += g_cnt[idx];
        }
    }
    if (tid == 1023) g_off[N_NODES] = part[1023];
}

// ---------------- CSR fill (+ norm computation) ------------------------------
__global__ void fill_kernel(const void* __restrict__ ei,
                            const float* __restrict__ ew) {
    int e = blockIdx.x * blockDim.x + threadIdx.x;
    if (e >= N_EDGES) return;
    int is64 = g_is64;
    int s = edge_at(ei, e, is64);
    int d = edge_at(ei, (size_t)N_EDGES + e, is64);
    float w = g_dis[s] * ew[e] * g_dis[d];
    int pos = atomicAdd(&g_cur[d], 1);
    g_csr_src[pos] = s;
    g_csr_w[pos] = w;
}

// ---------------- GEMM1: H1 = X @ W1 (tf32, cp.async double-buffered) --------
#define BM 128
#define BK 32
#define GT 320
#define ASTR 36   // A smem row stride (floats): conflict-free + 16B aligned

__global__ __launch_bounds__(GT)
void gemm1_kernel(const float* __restrict__ X, const float* __restrict__ W1) {
    extern __shared__ float sm[];
    float* As = sm;                      // 2 * BM * ASTR
    float* Bs = sm + 2 * BM * ASTR;      // 2 * BK * HID

    const int tid  = threadIdx.x;
    const int lane = tid & 31;
    const int warp = tid >> 5;
    const int gid  = lane >> 2;   // 0..7
    const int tig  = lane & 3;    // 0..3
    const int wm   = warp / 5;    // 0..1
    const int wn   = warp % 5;    // 0..4
    const int m0   = blockIdx.x * BM;
    const int NT   = (IN_DIM + BK - 1) / BK;  // 241

    float c[4][5][4];
#pragma unroll
    for (int mi = 0; mi < 4; mi++)
#pragma unroll
        for (int ni = 0; ni < 5; ni++)
#pragma unroll
            for (int r = 0; r < 4; r++) c[mi][ni][r] = 0.0f;

    auto load_tile = [&](int t, int buf) {
        const int k0 = t * BK;
        float* Ab = As + buf * BM * ASTR;
        float* Bb = Bs + buf * BK * HID;
        // A: 128 x 32 = 1024 quads
        for (int i = tid; i < BM * (BK / 4); i += GT) {
            int m = i >> 3, q = i & 7;
            int gm = m0 + m, gk = k0 + q * 4;
            const float* src = X;
            int sz = 0;
            if (gm < N_NODES && gk + 4 <= IN_DIM) {
                src = X + (size_t)gm * IN_DIM + gk;
                sz = 16;
            }
            cp16((unsigned)__cvta_generic_to_shared(Ab + m * ASTR + q * 4), src, sz);
        }
        // B: 32 x 200 = 1600 quads
        for (int i = tid; i < BK * (HID / 4); i += GT) {
            int kk = i / (HID / 4), q = i % (HID / 4);
            int gk = k0 + kk;
            const float* src = W1;
            int sz = 0;
            if (gk < IN_DIM) {
                src = W1 + (size_t)gk * HID + q * 4;
                sz = 16;
            }
            cp16((unsigned)__cvta_generic_to_shared(Bb + kk * HID + q * 4), src, sz);
        }
        asm volatile("cp.async.commit_group;\n");
    };

    load_tile(0, 0);
    for (int t = 0; t < NT; t++) {
        if (t + 1 < NT) {
            load_tile(t + 1, (t + 1) & 1);
            asm volatile("cp.async.wait_group 1;\n");
        } else {
            asm volatile("cp.async.wait_group 0;\n");
        }
        __syncthreads();
        const float* Ab = As + (t & 1) * BM * ASTR;
        const float* Bb = Bs + (t & 1) * BK * HID;

#pragma unroll
        for (int kk = 0; kk < BK; kk += 8) {
            unsigned a[4][4], b[5][2];
#pragma unroll
            for (int mi = 0; mi < 4; mi++) {
                int mr = wm * 64 + mi * 16 + gid;
                a[mi][0] = f2tf(Ab[mr * ASTR + kk + tig]);
                a[mi][1] = f2tf(Ab[(mr + 8) * ASTR + kk + tig]);
                a[mi][2] = f2tf(Ab[mr * ASTR + kk + tig + 4]);
                a[mi][3] = f2tf(Ab[(mr + 8) * ASTR + kk + tig + 4]);
            }
#pragma unroll
            for (int ni = 0; ni < 5; ni++) {
                int nc = wn * 40 + ni * 8 + gid;
                b[ni][0] = f2tf(Bb[(kk + tig) * HID + nc]);
                b[ni][1] = f2tf(Bb[(kk + tig + 4) * HID + nc]);
            }
#pragma unroll
            for (int mi = 0; mi < 4; mi++)
#pragma unroll
                for (int ni = 0; ni < 5; ni++) MMA_TF32(c[mi][ni], a[mi], b[ni]);
        }
        __syncthreads();
    }

    // epilogue: write H1
#pragma unroll
    for (int mi = 0; mi < 4; mi++) {
        int r0 = m0 + wm * 64 + mi * 16 + gid;
        int r1 = r0 + 8;
#pragma unroll
        for (int ni = 0; ni < 5; ni++) {
            int col = wn * 40 + ni * 8 + 2 * tig;
            if (r0 < N_NODES) {
                size_t o = (size_t)r0 * HID + col;
                g_H1[o]     = c[mi][ni][0];
                g_H1[o + 1] = c[mi][ni][1];
            }
            if (r1 < N_NODES) {
                size_t o = (size_t)r1 * HID + col;
                g_H1[o]     = c[mi][ni][2];
                g_H1[o + 1] = c[mi][ni][3];
            }
        }
    }
}

// ---------------- propagation 1: gather via CSR, fused bias+relu -------------
__global__ __launch_bounds__(224)
void prop1_kernel(const float* __restrict__ b1) {
    const int n = blockIdx.x;
    const int col = threadIdx.x;
    if (col >= HID) return;
    float dv = g_dis[n];
    float acc = g_H1[(size_t)n * HID + col] * (dv * dv);   // self loop
    int e = g_off[n], end = g_off[n + 1];
    for (; e + 2 <= end; e += 2) {
        int s0 = g_csr_src[e], s1 = g_csr_src[e + 1];
        float w0 = g_csr_w[e], w1 = g_csr_w[e + 1];
        acc += g_H1[(size_t)s0 * HID + col] * w0;
        acc += g_H1[(size_t)s1 * HID + col] * w1;
    }
    if (e < end)
        acc += g_H1[(size_t)g_csr_src[e] * HID + col] * g_csr_w[e];
    float v = acc + b1[col];
    g_h[(size_t)n * HID + col] = v > 0.f ? v : 0.f;
}

// ---------------- GEMM2: H2 = h @ W2 -----------------------------------------
__global__ void gemm2_kernel(const float* __restrict__ W2) {
    __shared__ float W2s[HID * OUT_DIM];
    int tid = threadIdx.x;
    for (int i = tid; i < HID * OUT_DIM; i += blockDim.x) W2s[i] = W2[i];
    __syncthreads();
    int row = blockIdx.x * blockDim.x + tid;
    if (row >= N_NODES) return;
    float acc[OUT_DIM];
#pragma unroll
    for (int o = 0; o < OUT_DIM; o++) acc[o] = 0.f;
    const float4* hq = reinterpret_cast<const float4*>(g_h + (size_t)row * HID);
#pragma unroll 2
    for (int q = 0; q < HID / 4; q++) {
        float4 v = hq[q];
        float hv[4] = {v.x, v.y, v.z, v.w};
#pragma unroll
        for (int j = 0; j < 4; j++) {
            int k = q * 4 + j;
#pragma unroll
            for (int o = 0; o < OUT_DIM; o++) acc[o] += hv[j] * W2s[k * OUT_DIM + o];
        }
    }
#pragma unroll
    for (int o = 0; o < OUT_DIM; o++)
        g_H2[(size_t)row * OUT_DIM + o] = acc[o];
}

// ---------------- propagation 2: gather via CSR (warp per node) --------------
__global__ void prop2_kernel(const float* __restrict__ b2,
                             float* __restrict__ outp) {
    int n = blockIdx.x * 4 + (threadIdx.x >> 5);
    if (n >= N_NODES) return;
    int lane = threadIdx.x & 31;
    int sub = lane >> 3;      // 0..3 edge groups
    int col = lane & 7;       // output column
    float acc = 0.f;
    int beg = g_off[n], end = g_off[n + 1];
    for (int e = beg + sub; e < end; e += 4)
        acc += g_H2[(size_t)g_csr_src[e] * OUT_DIM + col] * g_csr_w[e];
    acc += __shfl_xor_sync(0xffffffffu, acc, 8);
    acc += __shfl_xor_sync(0xffffffffu, acc, 16);
    if (sub == 0) {
        float dv = g_dis[n];
        outp[(size_t)n * OUT_DIM + col] =
            acc + g_H2[(size_t)n * OUT_DIM + col] * (dv * dv) + b2[col];
    }
}

// ---------------- launch -----------------------------------------------------
extern "C" void kernel_launch(void* const* d_in, const int* in_sizes, int n_in,
                              void* d_out, int out_size) {
    const float* x  = (const float*)d_in[0];
    const float* ew = (const float*)d_in[1];
    const float* W1 = (const float*)d_in[2];
    const float* b1 = (const float*)d_in[3];
    const float* W2 = (const float*)d_in[4];
    const float* b2 = (const float*)d_in[5];
    const void*  ei = d_in[6];
    float* outp = (float*)d_out;

    static int smem_set = 0;
    if (!smem_set) {
        cudaFuncSetAttribute(gemm1_kernel,
                             cudaFuncAttributeMaxDynamicSharedMemorySize,
                             (2 * BM * ASTR + 2 * BK * HID) * 4);
        smem_set = 1;
    }

    // launch order keeps gemm1 as the 6th launch (ncu -s 5 -c 1 profiles it)
    detect_kernel<<<1, 256>>>((const unsigned*)ei, 262144);
    init_kernel<<<(N_NODES + 255) / 256, 256>>>();
    accum_kernel<<<(N_EDGES + 255) / 256, 256>>>(ei, ew);
    rsqrt_kernel<<<(N_NODES + 255) / 256, 256>>>();
    scan_kernel<<<1, 1024>>>();
    gemm1_kernel<<<(N_NODES + BM - 1) / BM, GT,
                   (2 * BM * ASTR + 2 * BK * HID) * 4>>>(x, W1);
    fill_kernel<<<(N_EDGES + 255) / 256, 256>>>(ei, ew);
    prop1_kernel<<<N_NODES, 224>>>(b1);
    gemm2_kernel<<<(N_NODES + 255) / 256, 256>>>(W2);
    prop2_kernel<<<(N_NODES + 3) / 4, 128>>>(b2, outp);
}

// round 5
// speedup vs baseline: 3.1765x; 1.4113x over previous
#include <cuda_runtime.h>
#include <cuda_fp16.h>
#include <cstdint>

#define N_NODES 50000
#define IN_DIM  7688
#define HID     200
#define OUT_DIM 8
#define N_EDGES 1600000

// ---------------- scratch (device globals; no allocation allowed) -------------
__device__ float  g_dis[N_NODES];
__device__ int    g_cnt[N_NODES];
__device__ int    g_off[N_NODES + 1];
__device__ int    g_cur[N_NODES];
__device__ int    g_csr_src[N_EDGES];
__device__ float  g_csr_w[N_EDGES];
__device__ __half g_W1h[(size_t)HID * IN_DIM];      // W1^T in fp16, [n][k]
__device__ float  g_H1[(size_t)N_NODES * HID];
__device__ float  g_h[(size_t)N_NODES * HID];
__device__ float  g_H2[(size_t)N_NODES * OUT_DIM];
__device__ int    g_is64;

// ---------------- helpers ----------------------------------------------------
__device__ __forceinline__ int edge_at(const void* ei, size_t pos, int is64) {
    if (is64) return (int)((const long long*)ei)[pos];
    return ((const int*)ei)[pos];
}

__device__ __forceinline__ uint32_t smem_u32(const void* p) {
    uint32_t a;
    asm("{ .reg .u64 t; cvta.to.shared.u64 t, %1; cvt.u32.u64 %0, t; }"
        : "=r"(a) : "l"(p));
    return a;
}

__device__ __forceinline__ void cp16(uint32_t saddr, const void* g, int sz) {
    asm volatile("cp.async.cg.shared.global [%0], [%1], 16, %2;\n"
                 :: "r"(saddr), "l"(g), "r"(sz));
}

#define LDSM4(r0, r1, r2, r3, a)                                               \
    asm volatile("ldmatrix.sync.aligned.m8n8.x4.shared.b16 {%0,%1,%2,%3},[%4];"\
                 : "=r"(r0), "=r"(r1), "=r"(r2), "=r"(r3) : "r"(a))

#define LDSM2(r0, r1, a)                                                       \
    asm volatile("ldmatrix.sync.aligned.m8n8.x2.shared.b16 {%0,%1},[%2];"      \
                 : "=r"(r0), "=r"(r1) : "r"(a))

#define MMA16816(c, a, b)                                                      \
    asm volatile(                                                              \
        "mma.sync.aligned.m16n8k16.row.col.f32.f16.f16.f32 "                   \
        "{%0,%1,%2,%3},{%4,%5,%6,%7},{%8,%9},{%0,%1,%2,%3};\n"                 \
        : "+f"((c)[0]), "+f"((c)[1]), "+f"((c)[2]), "+f"((c)[3])               \
        : "r"((a)[0]), "r"((a)[1]), "r"((a)[2]), "r"((a)[3]),                  \
          "r"((b)[0]), "r"((b)[1]))

// ---------------- dtype detection --------------------------------------------
__global__ void detect_kernel(const unsigned* __restrict__ w, int n_check) {
    __shared__ int bad;
    if (threadIdx.x == 0) bad = 0;
    __syncthreads();
    int local = 0;
    for (int i = threadIdx.x; i < n_check; i += blockDim.x)
        if (w[2 * i + 1] != 0u) local = 1;
    if (local) bad = 1;
    __syncthreads();
    if (threadIdx.x == 0) g_is64 = bad ? 0 : 1;
}

// ---------------- degree + histogram init ------------------------------------
__global__ void init_kernel() {
    int i = blockIdx.x * blockDim.x + threadIdx.x;
    if (i < N_NODES) { g_dis[i] = 1.0f; g_cnt[i] = 0; }
}

// ---------------- W1 transpose + fp16 convert --------------------------------
__global__ void w1t_kernel(const float* __restrict__ W1) {
    __shared__ float tile[32][33];
    int kb = blockIdx.y * 32, nb = blockIdx.x * 32;
    for (int j = threadIdx.y; j < 32; j += 8) {
        int k = kb + j, n = nb + threadIdx.x;
        tile[j][threadIdx.x] =
            (k < IN_DIM && n < HID) ? W1[(size_t)k * HID + n] : 0.f;
    }
    __syncthreads();
    for (int j = threadIdx.y; j < 32; j += 8) {
        int n = nb + j, k = kb + threadIdx.x;
        if (n < HID && k < IN_DIM)
            g_W1h[(size_t)n * IN_DIM + k] = __float2half_rn(tile[threadIdx.x][j]);
    }
}

// ---------------- GEMM1: H1 = X @ W1 (fp16 HMMA, ldmatrix, double-buffered) ---
// 320 threads = 10 warps (2m x 5n), warp tile 64x40, block 128 x 200, BK=32.
#define G1T 320
#define G1_NT 241

__global__ __launch_bounds__(G1T, 1)
void gemm1_kernel(const float* __restrict__ X) {
    __shared__ __align__(16) unsigned char smA[2][128 * 64];   // 128 rows x 64B
    __shared__ __align__(16) unsigned char smB[2][200 * 64];   // 200 rows x 64B

    const int tid  = threadIdx.x;
    const int lane = tid & 31;
    const int warp = tid >> 5;
    const int gid  = lane >> 2;
    const int tig  = lane & 3;
    const int wm   = warp / 5;
    const int wn   = warp % 5;
    const int m0   = blockIdx.x * 128;

    // ---- A fill mapping: chunk i in [0,512): m=i>>2, c=i&3, 16B each --------
    const int i0 = tid;                 // chunk 0
    const int i1 = tid + G1T;           // chunk 1 (tid < 192 only)
    const int m_0 = i0 >> 2, c_0 = i0 & 3;
    const int m_1 = i1 >> 2, c_1 = i1 & 3;
    const bool has1 = (i1 < 512);
    const uint32_t dst0 = (uint32_t)(m_0 * 64 + ((c_0 ^ ((m_0 >> 1) & 3)) << 4));
    const uint32_t dst1 = (uint32_t)(m_1 * 64 + ((c_1 ^ ((m_1 >> 1) & 3)) << 4));
    const bool okm0 = (m0 + m_0) < N_NODES;
    const bool okm1 = has1 && ((m0 + m_1) < N_NODES);
    const float* rp0 = X + (size_t)(okm0 ? (m0 + m_0) : 0) * IN_DIM + c_0 * 8;
    const float* rp1 = X + (size_t)(okm1 ? (m0 + m_1) : 0) * IN_DIM + c_1 * 8;

    float4 v00, v01, v10, v11;
    auto ldgA = [&](int k0) {
        const float4 z = make_float4(0.f, 0.f, 0.f, 0.f);
        bool k_ok0 = (k0 + c_0 * 8 + 8) <= IN_DIM;
        bool k_ok1 = (k0 + c_1 * 8 + 8) <= IN_DIM;
        if (okm0 && k_ok0) {
            v00 = *reinterpret_cast<const float4*>(rp0 + k0);
            v01 = *reinterpret_cast<const float4*>(rp0 + k0 + 4);
        } else { v00 = z; v01 = z; }
        if (okm1 && k_ok1) {
            v10 = *reinterpret_cast<const float4*>(rp1 + k0);
            v11 = *reinterpret_cast<const float4*>(rp1 + k0 + 4);
        } else { v10 = z; v11 = z; }
    };
    auto stsA = [&](int buf) {
        __half2 h0 = __floats2half2_rn(v00.x, v00.y);
        __half2 h1 = __floats2half2_rn(v00.z, v00.w);
        __half2 h2 = __floats2half2_rn(v01.x, v01.y);
        __half2 h3 = __floats2half2_rn(v01.z, v01.w);
        *reinterpret_cast<uint4*>(smA[buf] + dst0) =
            make_uint4(*(uint32_t*)&h0, *(uint32_t*)&h1,
                       *(uint32_t*)&h2, *(uint32_t*)&h3);
        if (has1) {
            __half2 g0 = __floats2half2_rn(v10.x, v10.y);
            __half2 g1 = __floats2half2_rn(v10.z, v10.w);
            __half2 g2 = __floats2half2_rn(v11.x, v11.y);
            __half2 g3 = __floats2half2_rn(v11.z, v11.w);
            *reinterpret_cast<uint4*>(smA[buf] + dst1) =
                make_uint4(*(uint32_t*)&g0, *(uint32_t*)&g1,
                           *(uint32_t*)&g2, *(uint32_t*)&g3);
        }
    };
    auto cpB = [&](int k0, int buf) {
        const uint32_t bb = smem_u32(smB[buf]);
        for (int j = tid; j < 800; j += G1T) {
            int n = j >> 2, c = j & 3;
            int ok = (k0 + c * 8 + 8) <= IN_DIM;
            const __half* src = g_W1h + (size_t)n * IN_DIM + (ok ? (k0 + c * 8) : 0);
            cp16(bb + n * 64 + ((c ^ ((n >> 1) & 3)) << 4), src, ok ? 16 : 0);
        }
        asm volatile("cp.async.commit_group;\n");
    };

    // ---- fragment addresses (constant per thread) ---------------------------
    uint32_t aAddr[2][4], bAddr[2][5];
    {
        const int selA = ((lane & 15) >> 1) & 3;
        const int khalf = lane >> 4;
        const int selB = ((lane & 7) >> 1) & 3;
        const int bhalf = (lane >> 3) & 1;
        for (int buf = 0; buf < 2; buf++) {
            uint32_t ab = smem_u32(smA[buf]);
            uint32_t bb = smem_u32(smB[buf]);
#pragma unroll
            for (int mi = 0; mi < 4; mi++) {
                int row = wm * 64 + mi * 16 + (lane & 15);
                aAddr[buf][mi] = ab + row * 64 + (khalf ^ selA) * 0;  // base; chunk added per ks
                aAddr[buf][mi] = ab + row * 64;
            }
#pragma unroll
            for (int ni = 0; ni < 5; ni++) {
                int n = wn * 40 + ni * 8 + (lane & 7);
                bAddr[buf][ni] = bb + n * 64;
            }
        }
        // stash per-ks chunk offsets in registers below
        (void)selA; (void)khalf; (void)selB; (void)bhalf;
    }
    const int selA = ((lane & 15) >> 1) & 3;
    const int khalfA = lane >> 4;
    const int selB = ((lane & 7) >> 1) & 3;
    const int bhalfB = (lane >> 3) & 1;

    float c[4][5][4];
#pragma unroll
    for (int mi = 0; mi < 4; mi++)
#pragma unroll
        for (int ni = 0; ni < 5; ni++)
#pragma unroll
            for (int r = 0; r < 4; r++) c[mi][ni][r] = 0.0f;

    // ---- prologue -----------------------------------------------------------
    ldgA(0);
    stsA(0);
    cpB(0, 0);
    asm volatile("cp.async.wait_group 0;\n");
    __syncthreads();

    // ---- main loop ----------------------------------------------------------
    for (int t = 0; t < G1_NT; t++) {
        const int buf = t & 1;
        const bool more = (t + 1) < G1_NT;
        if (more) {
            ldgA((t + 1) * 32);
            cpB((t + 1) * 32, buf ^ 1);
        }
#pragma unroll
        for (int ks = 0; ks < 2; ks++) {
            uint32_t aoff = (uint32_t)(((ks * 2 + khalfA) ^ selA) << 4);
            uint32_t boff = (uint32_t)(((ks * 2 + bhalfB) ^ selB) << 4);
            uint32_t a[4][4], b[5][2];
#pragma unroll
            for (int mi = 0; mi < 4; mi++)
                LDSM4(a[mi][0], a[mi][1], a[mi][2], a[mi][3],
                      aAddr[buf][mi] + aoff);
#pragma unroll
            for (int ni = 0; ni < 5; ni++)
                LDSM2(b[ni][0], b[ni][1], bAddr[buf][ni] + boff);
#pragma unroll
            for (int mi = 0; mi < 4; mi++)
#pragma unroll
                for (int ni = 0; ni < 5; ni++) MMA16816(c[mi][ni], a[mi], b[ni]);
        }
        if (more) {
            stsA(buf ^ 1);
            asm volatile("cp.async.wait_group 0;\n");
        }
        __syncthreads();
    }

    // ---- epilogue -----------------------------------------------------------
#pragma unroll
    for (int mi = 0; mi < 4; mi++) {
        int r0 = m0 + wm * 64 + mi * 16 + gid;
        int r1 = r0 + 8;
#pragma unroll
        for (int ni = 0; ni < 5; ni++) {
            int col = wn * 40 + ni * 8 + 2 * tig;
            if (r0 < N_NODES)
                *reinterpret_cast<float2*>(g_H1 + (size_t)r0 * HID + col) =
                    make_float2(c[mi][ni][0], c[mi][ni][1]);
            if (r1 < N_NODES)
                *reinterpret_cast<float2*>(g_H1 + (size_t)r1 * HID + col) =
                    make_float2(c[mi][ni][2], c[mi][ni][3]);
        }
    }
}

// ---------------- degree accumulate ------------------------------------------
__global__ void accum_kernel(const void* __restrict__ ei,
                             const float* __restrict__ ew) {
    int e = blockIdx.x * blockDim.x + threadIdx.x;
    if (e >= N_EDGES) return;
    int is64 = g_is64;
    int d = edge_at(ei, (size_t)N_EDGES + e, is64);
    atomicAdd(&g_dis[d], ew[e]);
    atomicAdd(&g_cnt[d], 1);
}

__global__ void rsqrt_kernel() {
    int i = blockIdx.x * blockDim.x + threadIdx.x;
    if (i < N_NODES) {
        float dg = g_dis[i];
        g_dis[i] = (dg > 0.0f) ? rsqrtf(dg) : 0.0f;
    }
}

// ---------------- exclusive scan (single block) ------------------------------
__global__ void scan_kernel() {
    __shared__ int part[1024];
    const int tid = threadIdx.x;
    const int CH = (N_NODES + 1023) / 1024;
    int base = tid * CH;
    int s = 0;
    for (int i = 0; i < CH; i++) {
        int idx = base + i;
        if (idx < N_NODES) s += g_cnt[idx];
    }
    part[tid] = s;
    __syncthreads();
    for (int off = 1; off < 1024; off <<= 1) {
        int v = (tid >= off) ? part[tid - off] : 0;
        __syncthreads();
        part[tid] += v;
        __syncthreads();
    }
    int ex = part[tid] - s;
    for (int i = 0; i < CH; i++) {
        int idx = base + i;
        if (idx < N_NODES) {
            g_off[idx] = ex;
            g_cur[idx] = ex;
            ex += g_cnt[idx];
        }
    }
    if (tid == 1023) g_off[N_NODES] = part[1023];
}

// ---------------- CSR fill ----------------------------------------------------
__global__ void fill_kernel(const void* __restrict__ ei,
                            const float* __restrict__ ew) {
    int e = blockIdx.x * blockDim.x + threadIdx.x;
    if (e >= N_EDGES) return;
    int is64 = g_is64;
    int s = edge_at(ei, e, is64);
    int d = edge_at(ei, (size_t)N_EDGES + e, is64);
    float w = g_dis[s] * ew[e] * g_dis[d];
    int pos = atomicAdd(&g_cur[d], 1);
    g_csr_src[pos] = s;
    g_csr_w[pos] = w;
}

// ---------------- propagation 1: CSR gather + bias + relu --------------------
__global__ __launch_bounds__(224)
void prop1_kernel(const float* __restrict__ b1) {
    const int n = blockIdx.x;
    const int col = threadIdx.x;
    if (col >= HID) return;
    float dv = g_dis[n];
    float acc = g_H1[(size_t)n * HID + col] * (dv * dv);
    int e = g_off[n], end = g_off[n + 1];
    for (; e + 2 <= end; e += 2) {
        int s0 = g_csr_src[e], s1 = g_csr_src[e + 1];
        float w0 = g_csr_w[e], w1 = g_csr_w[e + 1];
        acc += g_H1[(size_t)s0 * HID + col] * w0;
        acc += g_H1[(size_t)s1 * HID + col] * w1;
    }
    if (e < end)
        acc += g_H1[(size_t)g_csr_src[e] * HID + col] * g_csr_w[e];
    float v = acc + b1[col];
    g_h[(size_t)n * HID + col] = v > 0.f ? v : 0.f;
}

// ---------------- GEMM2 -------------------------------------------------------
__global__ void gemm2_kernel(const float* __restrict__ W2) {
    __shared__ float W2s[HID * OUT_DIM];
    int tid = threadIdx.x;
    for (int i = tid; i < HID * OUT_DIM; i += blockDim.x) W2s[i] = W2[i];
    __syncthreads();
    int row = blockIdx.x * blockDim.x + tid;
    if (row >= N_NODES) return;
    float acc[OUT_DIM];
#pragma unroll
    for (int o = 0; o < OUT_DIM; o++) acc[o] = 0.f;
    const float4* hq = reinterpret_cast<const float4*>(g_h + (size_t)row * HID);
#pragma unroll 2
    for (int q = 0; q < HID / 4; q++) {
        float4 v = hq[q];
        float hv[4] = {v.x, v.y, v.z, v.w};
#pragma unroll
        for (int j = 0; j < 4; j++) {
            int k = q * 4 + j;
#pragma unroll
            for (int o = 0; o < OUT_DIM; o++) acc[o] += hv[j] * W2s[k * OUT_DIM + o];
        }
    }
#pragma unroll
    for (int o = 0; o < OUT_DIM; o++)
        g_H2[(size_t)row * OUT_DIM + o] = acc[o];
}

// ---------------- propagation 2 ----------------------------------------------
__global__ void prop2_kernel(const float* __restrict__ b2,
                             float* __restrict__ outp) {
    int n = blockIdx.x * 4 + (threadIdx.x >> 5);
    if (n >= N_NODES) return;
    int lane = threadIdx.x & 31;
    int sub = lane >> 3;
    int col = lane & 7;
    float acc = 0.f;
    int beg = g_off[n], end = g_off[n + 1];
    for (int e = beg + sub; e < end; e += 4)
        acc += g_H2[(size_t)g_csr_src[e] * OUT_DIM + col] * g_csr_w[e];
    acc += __shfl_xor_sync(0xffffffffu, acc, 8);
    acc += __shfl_xor_sync(0xffffffffu, acc, 16);
    if (sub == 0) {
        float dv = g_dis[n];
        outp[(size_t)n * OUT_DIM + col] =
            acc + g_H2[(size_t)n * OUT_DIM + col] * (dv * dv) + b2[col];
    }
}

// ---------------- launch -----------------------------------------------------
extern "C" void kernel_launch(void* const* d_in, const int* in_sizes, int n_in,
                              void* d_out, int out_size) {
    const float* x  = (const float*)d_in[0];
    const float* ew = (const float*)d_in[1];
    const float* W1 = (const float*)d_in[2];
    const float* b1 = (const float*)d_in[3];
    const float* W2 = (const float*)d_in[4];
    const float* b2 = (const float*)d_in[5];
    const void*  ei = d_in[6];
    float* outp = (float*)d_out;

    // gemm1 is the 4th launch: ncu (-s 5 -c 1) lands there
    detect_kernel<<<1, 256>>>((const unsigned*)ei, 262144);
    init_kernel<<<(N_NODES + 255) / 256, 256>>>();
    w1t_kernel<<<dim3((HID + 31) / 32, (IN_DIM + 31) / 32), dim3(32, 8)>>>(W1);
    gemm1_kernel<<<(N_NODES + 127) / 128, G1T>>>(x);
    accum_kernel<<<(N_EDGES + 255) / 256, 256>>>(ei, ew);
    rsqrt_kernel<<<(N_NODES + 255) / 256, 256>>>();
    scan_kernel<<<1, 1024>>>();
    fill_kernel<<<(N_EDGES + 255) / 256, 256>>>(ei, ew);
    prop1_kernel<<<N_NODES, 224>>>(b1);
    gemm2_kernel<<<(N_NODES + 255) / 256, 256>>>(W2);
    prop2_kernel<<<(N_NODES + 3) / 4, 128>>>(b2, outp);
}

// round 7
// speedup vs baseline: 4.7641x; 1.4998x over previous
#include <cuda_runtime.h>
#include <cuda_fp16.h>
#include <cstdint>

#define N_NODES 50000
#define IN_DIM  7688
#define HID     200
#define OUT_DIM 8
#define N_EDGES 1600000

// ---------------- scratch (device globals; no allocation allowed) -------------
__device__ float  g_dis[N_NODES];
__device__ int    g_cnt[N_NODES];
__device__ int    g_off[N_NODES + 1];
__device__ int    g_cur[N_NODES];
__device__ int    g_csr_src[N_EDGES];
__device__ float  g_csr_w[N_EDGES];
__device__ __half g_W1h[(size_t)HID * IN_DIM];      // W1^T in fp16, [n][k]
__device__ float  g_H1[(size_t)N_NODES * HID];
__device__ float  g_h[(size_t)N_NODES * HID];
__device__ float  g_H2[(size_t)N_NODES * OUT_DIM];
__device__ int    g_is64;

// ---------------- helpers ----------------------------------------------------
__device__ __forceinline__ int edge_at(const void* ei, size_t pos, int is64) {
    if (is64) return (int)((const long long*)ei)[pos];
    return ((const int*)ei)[pos];
}

__device__ __forceinline__ uint32_t smem_u32(const void* p) {
    uint32_t a;
    asm("{ .reg .u64 t; cvta.to.shared.u64 t, %1; cvt.u32.u64 %0, t; }"
        : "=r"(a) : "l"(p));
    return a;
}

__device__ __forceinline__ void cp16(uint32_t saddr, const void* g, int sz) {
    asm volatile("cp.async.cg.shared.global [%0], [%1], 16, %2;\n"
                 :: "r"(saddr), "l"(g), "r"(sz));
}

#define LDSM4(r0, r1, r2, r3, a)                                               \
    asm volatile("ldmatrix.sync.aligned.m8n8.x4.shared.b16 {%0,%1,%2,%3},[%4];"\
                 : "=r"(r0), "=r"(r1), "=r"(r2), "=r"(r3) : "r"(a))

#define LDSM2(r0, r1, a)                                                       \
    asm volatile("ldmatrix.sync.aligned.m8n8.x2.shared.b16 {%0,%1},[%2];"      \
                 : "=r"(r0), "=r"(r1) : "r"(a))

#define MMA16816(c, a, b)                                                      \
    asm volatile(                                                              \
        "mma.sync.aligned.m16n8k16.row.col.f32.f16.f16.f32 "                   \
        "{%0,%1,%2,%3},{%4,%5,%6,%7},{%8,%9},{%0,%1,%2,%3};\n"                 \
        : "+f"((c)[0]), "+f"((c)[1]), "+f"((c)[2]), "+f"((c)[3])               \
        : "r"((a)[0]), "r"((a)[1]), "r"((a)[2]), "r"((a)[3]),                  \
          "r"((b)[0]), "r"((b)[1]))

// ---------------- dtype detection --------------------------------------------
__global__ void detect_kernel(const unsigned* __restrict__ w, int n_check) {
    __shared__ int bad;
    if (threadIdx.x == 0) bad = 0;
    __syncthreads();
    int local = 0;
    for (int i = threadIdx.x; i < n_check; i += blockDim.x)
        if (w[2 * i + 1] != 0u) local = 1;
    if (local) bad = 1;
    __syncthreads();
    if (threadIdx.x == 0) g_is64 = bad ? 0 : 1;
}

// ---------------- degree + histogram init ------------------------------------
__global__ void init_kernel() {
    int i = blockIdx.x * blockDim.x + threadIdx.x;
    if (i < N_NODES) { g_dis[i] = 1.0f; g_cnt[i] = 0; }
}

// ---------------- W1 transpose + fp16 convert --------------------------------
__global__ void w1t_kernel(const float* __restrict__ W1) {
    __shared__ float tile[32][33];
    int kb = blockIdx.y * 32, nb = blockIdx.x * 32;
    for (int j = threadIdx.y; j < 32; j += 8) {
        int k = kb + j, n = nb + threadIdx.x;
        tile[j][threadIdx.x] =
            (k < IN_DIM && n < HID) ? W1[(size_t)k * HID + n] : 0.f;
    }
    __syncthreads();
    for (int j = threadIdx.y; j < 32; j += 8) {
        int n = nb + j, k = kb + threadIdx.x;
        if (n < HID && k < IN_DIM)
            g_W1h[(size_t)n * IN_DIM + k] = __float2half_rn(tile[threadIdx.x][j]);
    }
}

// ---------------- GEMM1: H1 = X @ W1 (fp16 HMMA, ldmatrix, double-buffered) ---
#define G1T 320
#define G1_NT 241

__global__ __launch_bounds__(G1T, 1)
void gemm1_kernel(const float* __restrict__ X) {
    __shared__ __align__(16) unsigned char smA[2][128 * 64];
    __shared__ __align__(16) unsigned char smB[2][200 * 64];

    const int tid  = threadIdx.x;
    const int lane = tid & 31;
    const int warp = tid >> 5;
    const int gid  = lane >> 2;
    const int tig  = lane & 3;
    const int wm   = warp / 5;
    const int wn   = warp % 5;
    const int m0   = blockIdx.x * 128;

    const int i0 = tid;
    const int i1 = tid + G1T;
    const int m_0 = i0 >> 2, c_0 = i0 & 3;
    const int m_1 = i1 >> 2, c_1 = i1 & 3;
    const bool has1 = (i1 < 512);
    const uint32_t dst0 = (uint32_t)(m_0 * 64 + ((c_0 ^ ((m_0 >> 1) & 3)) << 4));
    const uint32_t dst1 = (uint32_t)(m_1 * 64 + ((c_1 ^ ((m_1 >> 1) & 3)) << 4));
    const bool okm0 = (m0 + m_0) < N_NODES;
    const bool okm1 = has1 && ((m0 + m_1) < N_NODES);
    const float* rp0 = X + (size_t)(okm0 ? (m0 + m_0) : 0) * IN_DIM + c_0 * 8;
    const float* rp1 = X + (size_t)(okm1 ? (m0 + m_1) : 0) * IN_DIM + c_1 * 8;

    float4 v00, v01, v10, v11;
    auto ldgA = [&](int k0) {
        const float4 z = make_float4(0.f, 0.f, 0.f, 0.f);
        bool k_ok0 = (k0 + c_0 * 8 + 8) <= IN_DIM;
        bool k_ok1 = (k0 + c_1 * 8 + 8) <= IN_DIM;
        if (okm0 && k_ok0) {
            v00 = *reinterpret_cast<const float4*>(rp0 + k0);
            v01 = *reinterpret_cast<const float4*>(rp0 + k0 + 4);
        } else { v00 = z; v01 = z; }
        if (okm1 && k_ok1) {
            v10 = *reinterpret_cast<const float4*>(rp1 + k0);
            v11 = *reinterpret_cast<const float4*>(rp1 + k0 + 4);
        } else { v10 = z; v11 = z; }
    };
    auto stsA = [&](int buf) {
        __half2 h0 = __floats2half2_rn(v00.x, v00.y);
        __half2 h1 = __floats2half2_rn(v00.z, v00.w);
        __half2 h2 = __floats2half2_rn(v01.x, v01.y);
        __half2 h3 = __floats2half2_rn(v01.z, v01.w);
        *reinterpret_cast<uint4*>(smA[buf] + dst0) =
            make_uint4(*(uint32_t*)&h0, *(uint32_t*)&h1,
                       *(uint32_t*)&h2, *(uint32_t*)&h3);
        if (has1) {
            __half2 g0 = __floats2half2_rn(v10.x, v10.y);
            __half2 g1 = __floats2half2_rn(v10.z, v10.w);
            __half2 g2 = __floats2half2_rn(v11.x, v11.y);
            __half2 g3 = __floats2half2_rn(v11.z, v11.w);
            *reinterpret_cast<uint4*>(smA[buf] + dst1) =
                make_uint4(*(uint32_t*)&g0, *(uint32_t*)&g1,
                           *(uint32_t*)&g2, *(uint32_t*)&g3);
        }
    };
    auto cpB = [&](int k0, int buf) {
        const uint32_t bb = smem_u32(smB[buf]);
        for (int j = tid; j < 800; j += G1T) {
            int n = j >> 2, c = j & 3;
            int ok = (k0 + c * 8 + 8) <= IN_DIM;
            const __half* src = g_W1h + (size_t)n * IN_DIM + (ok ? (k0 + c * 8) : 0);
            cp16(bb + n * 64 + ((c ^ ((n >> 1) & 3)) << 4), src, ok ? 16 : 0);
        }
        asm volatile("cp.async.commit_group;\n");
    };

    uint32_t aAddr[2][4], bAddr[2][5];
    for (int buf = 0; buf < 2; buf++) {
        uint32_t ab = smem_u32(smA[buf]);
        uint32_t bb = smem_u32(smB[buf]);
#pragma unroll
        for (int mi = 0; mi < 4; mi++) {
            int row = wm * 64 + mi * 16 + (lane & 15);
            aAddr[buf][mi] = ab + row * 64;
        }
#pragma unroll
        for (int ni = 0; ni < 5; ni++) {
            int n = wn * 40 + ni * 8 + (lane & 7);
            bAddr[buf][ni] = bb + n * 64;
        }
    }
    const int selA = ((lane & 15) >> 1) & 3;
    const int khalfA = lane >> 4;
    const int selB = ((lane & 7) >> 1) & 3;
    const int bhalfB = (lane >> 3) & 1;

    float c[4][5][4];
#pragma unroll
    for (int mi = 0; mi < 4; mi++)
#pragma unroll
        for (int ni = 0; ni < 5; ni++)
#pragma unroll
            for (int r = 0; r < 4; r++) c[mi][ni][r] = 0.0f;

    ldgA(0);
    stsA(0);
    cpB(0, 0);
    asm volatile("cp.async.wait_group 0;\n");
    __syncthreads();

    for (int t = 0; t < G1_NT; t++) {
        const int buf = t & 1;
        const bool more = (t + 1) < G1_NT;
        if (more) {
            ldgA((t + 1) * 32);
            cpB((t + 1) * 32, buf ^ 1);
        }
        // stage ALL fragments for both k-steps, then run MMAs back-to-back
        uint32_t a[2][4][4], b[2][5][2];
#pragma unroll
        for (int ks = 0; ks < 2; ks++) {
            uint32_t aoff = (uint32_t)(((ks * 2 + khalfA) ^ selA) << 4);
            uint32_t boff = (uint32_t)(((ks * 2 + bhalfB) ^ selB) << 4);
#pragma unroll
            for (int mi = 0; mi < 4; mi++)
                LDSM4(a[ks][mi][0], a[ks][mi][1], a[ks][mi][2], a[ks][mi][3],
                      aAddr[buf][mi] + aoff);
#pragma unroll
            for (int ni = 0; ni < 5; ni++)
                LDSM2(b[ks][ni][0], b[ks][ni][1], bAddr[buf][ni] + boff);
        }
#pragma unroll
        for (int ks = 0; ks < 2; ks++)
#pragma unroll
            for (int mi = 0; mi < 4; mi++)
#pragma unroll
                for (int ni = 0; ni < 5; ni++)
                    MMA16816(c[mi][ni], a[ks][mi], b[ks][ni]);
        if (more) {
            stsA(buf ^ 1);
            asm volatile("cp.async.wait_group 0;\n");
        }
        __syncthreads();
    }

#pragma unroll
    for (int mi = 0; mi < 4; mi++) {
        int r0 = m0 + wm * 64 + mi * 16 + gid;
        int r1 = r0 + 8;
#pragma unroll
        for (int ni = 0; ni < 5; ni++) {
            int col = wn * 40 + ni * 8 + 2 * tig;
            if (r0 < N_NODES)
                *reinterpret_cast<float2*>(g_H1 + (size_t)r0 * HID + col) =
                    make_float2(c[mi][ni][0], c[mi][ni][1]);
            if (r1 < N_NODES)
                *reinterpret_cast<float2*>(g_H1 + (size_t)r1 * HID + col) =
                    make_float2(c[mi][ni][2], c[mi][ni][3]);
        }
    }
}

// ---------------- degree accumulate ------------------------------------------
__global__ void accum_kernel(const void* __restrict__ ei,
                             const float* __restrict__ ew) {
    int e = blockIdx.x * blockDim.x + threadIdx.x;
    if (e >= N_EDGES) return;
    int is64 = g_is64;
    int d = edge_at(ei, (size_t)N_EDGES + e, is64);
    atomicAdd(&g_dis[d], ew[e]);
    atomicAdd(&g_cnt[d], 1);
}

__global__ void rsqrt_kernel() {
    int i = blockIdx.x * blockDim.x + threadIdx.x;
    if (i < N_NODES) {
        float dg = g_dis[i];
        g_dis[i] = (dg > 0.0f) ? rsqrtf(dg) : 0.0f;
    }
}

// ---------------- exclusive scan (single block) ------------------------------
__global__ void scan_kernel() {
    __shared__ int part[1024];
    const int tid = threadIdx.x;
    const int CH = (N_NODES + 1023) / 1024;
    int base = tid * CH;
    int s = 0;
    for (int i = 0; i < CH; i++) {
        int idx = base + i;
        if (idx < N_NODES) s += g_cnt[idx];
    }
    part[tid] = s;
    __syncthreads();
    for (int off = 1; off < 1024; off <<= 1) {
        int v = (tid >= off) ? part[tid - off] : 0;
        __syncthreads();
        part[tid] += v;
        __syncthreads();
    }
    int ex = part[tid] - s;
    for (int i = 0; i < CH; i++) {
        int idx = base + i;
        if (idx < N_NODES) {
            g_off[idx] = ex;
            g_cur[idx] = ex;
            ex += g_cnt[idx];
        }
    }
    if (tid == 1023) g_off[N_NODES] = part[1023];
}

// ---------------- CSR fill ----------------------------------------------------
__global__ void fill_kernel(const void* __restrict__ ei,
                            const float* __restrict__ ew) {
    int e = blockIdx.x * blockDim.x + threadIdx.x;
    if (e >= N_EDGES) return;
    int is64 = g_is64;
    int s = edge_at(ei, e, is64);
    int d = edge_at(ei, (size_t)N_EDGES + e, is64);
    float w = g_dis[s] * ew[e] * g_dis[d];
    int pos = atomicAdd(&g_cur[d], 1);
    g_csr_src[pos] = s;
    g_csr_w[pos] = w;
}

// ---------------- propagation 1: CSR gather + bias + relu --------------------
__global__ __launch_bounds__(224)
void prop1_kernel(const float* __restrict__ b1) {
    const int n = blockIdx.x;
    const int col = threadIdx.x;
    if (col >= HID) return;
    float dv = g_dis[n];
    float acc = g_H1[(size_t)n * HID + col] * (dv * dv);
    int e = g_off[n], end = g_off[n + 1];
    for (; e + 4 <= end; e += 4) {
        int s0 = g_csr_src[e],     s1 = g_csr_src[e + 1];
        int s2 = g_csr_src[e + 2], s3 = g_csr_src[e + 3];
        float w0 = g_csr_w[e],     w1 = g_csr_w[e + 1];
        float w2 = g_csr_w[e + 2], w3 = g_csr_w[e + 3];
        float x0 = g_H1[(size_t)s0 * HID + col];
        float x1 = g_H1[(size_t)s1 * HID + col];
        float x2 = g_H1[(size_t)s2 * HID + col];
        float x3 = g_H1[(size_t)s3 * HID + col];
        acc += x0 * w0 + x1 * w1 + x2 * w2 + x3 * w3;
    }
    for (; e < end; e++)
        acc += g_H1[(size_t)g_csr_src[e] * HID + col] * g_csr_w[e];
    float v = acc + b1[col];
    g_h[(size_t)n * HID + col] = v > 0.f ? v : 0.f;
}

// ---------------- GEMM2 -------------------------------------------------------
__global__ void gemm2_kernel(const float* __restrict__ W2) {
    __shared__ float W2s[HID * OUT_DIM];
    int tid = threadIdx.x;
    for (int i = tid; i < HID * OUT_DIM; i += blockDim.x) W2s[i] = W2[i];
    __syncthreads();
    int row = blockIdx.x * blockDim.x + tid;
    if (row >= N_NODES) return;
    float acc[OUT_DIM];
#pragma unroll
    for (int o = 0; o < OUT_DIM; o++) acc[o] = 0.f;
    const float4* hq = reinterpret_cast<const float4*>(g_h + (size_t)row * HID);
#pragma unroll 5
    for (int q = 0; q < HID / 4; q++) {
        float4 v = hq[q];
        float hv[4] = {v.x, v.y, v.z, v.w};
#pragma unroll
        for (int j = 0; j < 4; j++) {
            int k = q * 4 + j;
#pragma unroll
            for (int o = 0; o < OUT_DIM; o++) acc[o] += hv[j] * W2s[k * OUT_DIM + o];
        }
    }
#pragma unroll
    for (int o = 0; o < OUT_DIM; o++)
        g_H2[(size_t)row * OUT_DIM + o] = acc[o];
}

// ---------------- propagation 2 ----------------------------------------------
__global__ void prop2_kernel(const float* __restrict__ b2,
                             float* __restrict__ outp) {
    int n = blockIdx.x * 4 + (threadIdx.x >> 5);
    if (n >= N_NODES) return;
    int lane = threadIdx.x & 31;
    int sub = lane >> 3;
    int col = lane & 7;
    float acc = 0.f;
    int beg = g_off[n], end = g_off[n + 1];
    for (int e = beg + sub; e < end; e += 4)
        acc += g_H2[(size_t)g_csr_src[e] * OUT_DIM + col] * g_csr_w[e];
    acc += __shfl_xor_sync(0xffffffffu, acc, 8);
    acc += __shfl_xor_sync(0xffffffffu, acc, 16);
    if (sub == 0) {
        float dv = g_dis[n];
        outp[(size_t)n * OUT_DIM + col] =
            acc + g_H2[(size_t)n * OUT_DIM + col] * (dv * dv) + b2[col];
    }
}

// ---------------- launch -----------------------------------------------------
extern "C" void kernel_launch(void* const* d_in, const int* in_sizes, int n_in,
                              void* d_out, int out_size) {
    const float* x  = (const float*)d_in[0];
    const float* ew = (const float*)d_in[1];
    const float* W1 = (const float*)d_in[2];
    const float* b1 = (const float*)d_in[3];
    const float* W2 = (const float*)d_in[4];
    const float* b2 = (const float*)d_in[5];
    const void*  ei = d_in[6];
    float* outp = (float*)d_out;

    // side stream + events, created once in the (uncaptured) correctness call
    static cudaStream_t s1 = nullptr;
    static cudaEvent_t evFork = nullptr, evJoin = nullptr;
    if (!s1) {
        cudaStreamCreateWithFlags(&s1, cudaStreamNonBlocking);
        cudaEventCreateWithFlags(&evFork, cudaEventDisableTiming);
        cudaEventCreateWithFlags(&evJoin, cudaEventDisableTiming);
    }

    // fork: edge/CSR pipeline on s1, GEMM pipeline on stream 0
    cudaEventRecord(evFork, 0);
    cudaStreamWaitEvent(s1, evFork, 0);

    detect_kernel<<<1, 256, 0, s1>>>((const unsigned*)ei, 4096);
    init_kernel<<<(N_NODES + 255) / 256, 256, 0, s1>>>();
    w1t_kernel<<<dim3((HID + 31) / 32, (IN_DIM + 31) / 32), dim3(32, 8)>>>(W1);
    gemm1_kernel<<<(N_NODES + 127) / 128, G1T>>>(x);
    accum_kernel<<<(N_EDGES + 255) / 256, 256, 0, s1>>>(ei, ew);
    rsqrt_kernel<<<(N_NODES + 255) / 256, 256, 0, s1>>>();
    scan_kernel<<<1, 1024, 0, s1>>>();
    fill_kernel<<<(N_EDGES + 255) / 256, 256, 0, s1>>>(ei, ew);

    // join: prop1 needs H1 (stream 0) + CSR (s1)
    cudaEventRecord(evJoin, s1);
    cudaStreamWaitEvent(0, evJoin, 0);

    prop1_kernel<<<N_NODES, 224>>>(b1);
    gemm2_kernel<<<(N_NODES + 255) / 256, 256>>>(W2);
    prop2_kernel<<<(N_NODES + 3) / 4, 128>>>(b2, outp);
}

// round 8
// speedup vs baseline: 4.9932x; 1.0481x over previous
#include <cuda_runtime.h>
#include <cuda_fp16.h>
#include <cstdint>

#define N_NODES 50000
#define IN_DIM  7688
#define HID     200
#define OUT_DIM 8
#define N_EDGES 1600000

// ---------------- scratch (device globals; no allocation allowed) -------------
__device__ float  g_dis[N_NODES];
__device__ int    g_cnt[N_NODES];
__device__ int    g_off[N_NODES + 1];
__device__ int    g_cur[N_NODES];
__device__ int    g_csr_src[N_EDGES];
__device__ float  g_csr_w[N_EDGES];
__device__ __half g_W1h[(size_t)HID * IN_DIM];      // W1^T in fp16, [n][k]
__device__ float  g_H1[(size_t)N_NODES * HID];
__device__ float  g_h[(size_t)N_NODES * HID];
__device__ float  g_H2[(size_t)N_NODES * OUT_DIM];
__device__ int    g_is64;

// ---------------- helpers ----------------------------------------------------
__device__ __forceinline__ int edge_at(const void* ei, size_t pos, int is64) {
    if (is64) return (int)((const long long*)ei)[pos];
    return ((const int*)ei)[pos];
}

__device__ __forceinline__ uint32_t smem_u32(const void* p) {
    uint32_t a;
    asm("{ .reg .u64 t; cvta.to.shared.u64 t, %1; cvt.u32.u64 %0, t; }"
        : "=r"(a) : "l"(p));
    return a;
}

__device__ __forceinline__ void cp16(uint32_t saddr, const void* g, int sz) {
    asm volatile("cp.async.cg.shared.global [%0], [%1], 16, %2;\n"
                 :: "r"(saddr), "l"(g), "r"(sz));
}

#define LDSM4(r0, r1, r2, r3, a)                                               \
    asm volatile("ldmatrix.sync.aligned.m8n8.x4.shared.b16 {%0,%1,%2,%3},[%4];"\
                 : "=r"(r0), "=r"(r1), "=r"(r2), "=r"(r3) : "r"(a))

#define LDSM2(r0, r1, a)                                                       \
    asm volatile("ldmatrix.sync.aligned.m8n8.x2.shared.b16 {%0,%1},[%2];"      \
                 : "=r"(r0), "=r"(r1) : "r"(a))

#define MMA16816(c, a, b)                                                      \
    asm volatile(                                                              \
        "mma.sync.aligned.m16n8k16.row.col.f32.f16.f16.f32 "                   \
        "{%0,%1,%2,%3},{%4,%5,%6,%7},{%8,%9},{%0,%1,%2,%3};\n"                 \
        : "+f"((c)[0]), "+f"((c)[1]), "+f"((c)[2]), "+f"((c)[3])               \
        : "r"((a)[0]), "r"((a)[1]), "r"((a)[2]), "r"((a)[3]),                  \
          "r"((b)[0]), "r"((b)[1]))

// ---------------- dtype detection --------------------------------------------
__global__ void detect_kernel(const unsigned* __restrict__ w, int n_check) {
    __shared__ int bad;
    if (threadIdx.x == 0) bad = 0;
    __syncthreads();
    int local = 0;
    for (int i = threadIdx.x; i < n_check; i += blockDim.x)
        if (w[2 * i + 1] != 0u) local = 1;
    if (local) bad = 1;
    __syncthreads();
    if (threadIdx.x == 0) g_is64 = bad ? 0 : 1;
}

// ---------------- degree + histogram init ------------------------------------
__global__ void init_kernel() {
    int i = blockIdx.x * blockDim.x + threadIdx.x;
    if (i < N_NODES) { g_dis[i] = 1.0f; g_cnt[i] = 0; }
}

// ---------------- W1 transpose + fp16 convert --------------------------------
__global__ void w1t_kernel(const float* __restrict__ W1) {
    __shared__ float tile[32][33];
    int kb = blockIdx.y * 32, nb = blockIdx.x * 32;
    for (int j = threadIdx.y; j < 32; j += 8) {
        int k = kb + j, n = nb + threadIdx.x;
        tile[j][threadIdx.x] =
            (k < IN_DIM && n < HID) ? W1[(size_t)k * HID + n] : 0.f;
    }
    __syncthreads();
    for (int j = threadIdx.y; j < 32; j += 8) {
        int n = nb + j, k = kb + threadIdx.x;
        if (n < HID && k < IN_DIM)
            g_W1h[(size_t)n * IN_DIM + k] = __float2half_rn(tile[threadIdx.x][j]);
    }
}

// ---------------- GEMM1: H1 = X @ W1 (fp16 HMMA, 64x200 CTA, 2 CTAs/SM) ------
#define G1T   160     // 5 warps, each 64x40
#define G1_BM 64
#define G1_NT 241

__global__ __launch_bounds__(G1T, 2)
void gemm1_kernel(const float* __restrict__ X) {
    __shared__ __align__(16) unsigned char smA[2][G1_BM * 64];
    __shared__ __align__(16) unsigned char smB[2][200 * 64];

    const int tid  = threadIdx.x;
    const int lane = tid & 31;
    const int warp = tid >> 5;          // 0..4 = n-slot
    const int gid  = lane >> 2;
    const int tig  = lane & 3;
    const int wn   = warp;
    const int m0   = blockIdx.x * G1_BM;

    // A fill: 64 rows x 4 chunks(16B) = 256 chunks
    const int i0 = tid;
    const int i1 = tid + G1T;
    const int m_0 = i0 >> 2, c_0 = i0 & 3;
    const int m_1 = i1 >> 2, c_1 = i1 & 3;
    const bool has1 = (i1 < G1_BM * 4);
    const uint32_t dst0 = (uint32_t)(m_0 * 64 + ((c_0 ^ ((m_0 >> 1) & 3)) << 4));
    const uint32_t dst1 = (uint32_t)(m_1 * 64 + ((c_1 ^ ((m_1 >> 1) & 3)) << 4));
    const bool okm0 = (m0 + m_0) < N_NODES;
    const bool okm1 = has1 && ((m0 + m_1) < N_NODES);
    const float* rp0 = X + (size_t)(okm0 ? (m0 + m_0) : 0) * IN_DIM + c_0 * 8;
    const float* rp1 = X + (size_t)(okm1 ? (m0 + m_1) : 0) * IN_DIM + c_1 * 8;

    float4 v00, v01, v10, v11;
    auto ldgA = [&](int k0) {
        const float4 z = make_float4(0.f, 0.f, 0.f, 0.f);
        bool k_ok0 = (k0 + c_0 * 8 + 8) <= IN_DIM;
        bool k_ok1 = (k0 + c_1 * 8 + 8) <= IN_DIM;
        if (okm0 && k_ok0) {
            v00 = *reinterpret_cast<const float4*>(rp0 + k0);
            v01 = *reinterpret_cast<const float4*>(rp0 + k0 + 4);
        } else { v00 = z; v01 = z; }
        if (okm1 && k_ok1) {
            v10 = *reinterpret_cast<const float4*>(rp1 + k0);
            v11 = *reinterpret_cast<const float4*>(rp1 + k0 + 4);
        } else { v10 = z; v11 = z; }
    };
    auto stsA = [&](int buf) {
        __half2 h0 = __floats2half2_rn(v00.x, v00.y);
        __half2 h1 = __floats2half2_rn(v00.z, v00.w);
        __half2 h2 = __floats2half2_rn(v01.x, v01.y);
        __half2 h3 = __floats2half2_rn(v01.z, v01.w);
        *reinterpret_cast<uint4*>(smA[buf] + dst0) =
            make_uint4(*(uint32_t*)&h0, *(uint32_t*)&h1,
                       *(uint32_t*)&h2, *(uint32_t*)&h3);
        if (has1) {
            __half2 g0 = __floats2half2_rn(v10.x, v10.y);
            __half2 g1 = __floats2half2_rn(v10.z, v10.w);
            __half2 g2 = __floats2half2_rn(v11.x, v11.y);
            __half2 g3 = __floats2half2_rn(v11.z, v11.w);
            *reinterpret_cast<uint4*>(smA[buf] + dst1) =
                make_uint4(*(uint32_t*)&g0, *(uint32_t*)&g1,
                           *(uint32_t*)&g2, *(uint32_t*)&g3);
        }
    };
    auto cpB = [&](int k0, int buf) {
        const uint32_t bb = smem_u32(smB[buf]);
        for (int j = tid; j < 800; j += G1T) {
            int n = j >> 2, c = j & 3;
            int ok = (k0 + c * 8 + 8) <= IN_DIM;
            const __half* src = g_W1h + (size_t)n * IN_DIM + (ok ? (k0 + c * 8) : 0);
            cp16(bb + n * 64 + ((c ^ ((n >> 1) & 3)) << 4), src, ok ? 16 : 0);
        }
        asm volatile("cp.async.commit_group;\n");
    };

    uint32_t aAddr[2][4], bAddr[2][5];
    for (int buf = 0; buf < 2; buf++) {
        uint32_t ab = smem_u32(smA[buf]);
        uint32_t bb = smem_u32(smB[buf]);
#pragma unroll
        for (int mi = 0; mi < 4; mi++) {
            int row = mi * 16 + (lane & 15);
            aAddr[buf][mi] = ab + row * 64;
        }
#pragma unroll
        for (int ni = 0; ni < 5; ni++) {
            int n = wn * 40 + ni * 8 + (lane & 7);
            bAddr[buf][ni] = bb + n * 64;
        }
    }
    const int selA = ((lane & 15) >> 1) & 3;
    const int khalfA = lane >> 4;
    const int selB = ((lane & 7) >> 1) & 3;
    const int bhalfB = (lane >> 3) & 1;

    float c[4][5][4];
#pragma unroll
    for (int mi = 0; mi < 4; mi++)
#pragma unroll
        for (int ni = 0; ni < 5; ni++)
#pragma unroll
            for (int r = 0; r < 4; r++) c[mi][ni][r] = 0.0f;

    ldgA(0);
    stsA(0);
    cpB(0, 0);
    asm volatile("cp.async.wait_group 0;\n");
    __syncthreads();

    for (int t = 0; t < G1_NT; t++) {
        const int buf = t & 1;
        const bool more = (t + 1) < G1_NT;
        if (more) {
            ldgA((t + 1) * 32);
            cpB((t + 1) * 32, buf ^ 1);
        }
        uint32_t a[2][4][4], b[2][5][2];
#pragma unroll
        for (int ks = 0; ks < 2; ks++) {
            uint32_t aoff = (uint32_t)(((ks * 2 + khalfA) ^ selA) << 4);
            uint32_t boff = (uint32_t)(((ks * 2 + bhalfB) ^ selB) << 4);
#pragma unroll
            for (int mi = 0; mi < 4; mi++)
                LDSM4(a[ks][mi][0], a[ks][mi][1], a[ks][mi][2], a[ks][mi][3],
                      aAddr[buf][mi] + aoff);
#pragma unroll
            for (int ni = 0; ni < 5; ni++)
                LDSM2(b[ks][ni][0], b[ks][ni][1], bAddr[buf][ni] + boff);
        }
#pragma unroll
        for (int ks = 0; ks < 2; ks++)
#pragma unroll
            for (int mi = 0; mi < 4; mi++)
#pragma unroll
                for (int ni = 0; ni < 5; ni++)
                    MMA16816(c[mi][ni], a[ks][mi], b[ks][ni]);
        if (more) {
            stsA(buf ^ 1);
            asm volatile("cp.async.wait_group 0;\n");
        }
        __syncthreads();
    }

#pragma unroll
    for (int mi = 0; mi < 4; mi++) {
        int r0 = m0 + mi * 16 + gid;
        int r1 = r0 + 8;
#pragma unroll
        for (int ni = 0; ni < 5; ni++) {
            int col = wn * 40 + ni * 8 + 2 * tig;
            if (r0 < N_NODES)
                *reinterpret_cast<float2*>(g_H1 + (size_t)r0 * HID + col) =
                    make_float2(c[mi][ni][0], c[mi][ni][1]);
            if (r1 < N_NODES)
                *reinterpret_cast<float2*>(g_H1 + (size_t)r1 * HID + col) =
                    make_float2(c[mi][ni][2], c[mi][ni][3]);
        }
    }
}

// ---------------- degree accumulate ------------------------------------------
__global__ void accum_kernel(const void* __restrict__ ei,
                             const float* __restrict__ ew) {
    int e = blockIdx.x * blockDim.x + threadIdx.x;
    if (e >= N_EDGES) return;
    int is64 = g_is64;
    int d = edge_at(ei, (size_t)N_EDGES + e, is64);
    atomicAdd(&g_dis[d], ew[e]);
    atomicAdd(&g_cnt[d], 1);
}

__global__ void rsqrt_kernel() {
    int i = blockIdx.x * blockDim.x + threadIdx.x;
    if (i < N_NODES) {
        float dg = g_dis[i];
        g_dis[i] = (dg > 0.0f) ? rsqrtf(dg) : 0.0f;
    }
}

// ---------------- exclusive scan (single block) ------------------------------
__global__ void scan_kernel() {
    __shared__ int part[1024];
    const int tid = threadIdx.x;
    const int CH = (N_NODES + 1023) / 1024;
    int base = tid * CH;
    int s = 0;
    for (int i = 0; i < CH; i++) {
        int idx = base + i;
        if (idx < N_NODES) s += g_cnt[idx];
    }
    part[tid] = s;
    __syncthreads();
    for (int off = 1; off < 1024; off <<= 1) {
        int v = (tid >= off) ? part[tid - off] : 0;
        __syncthreads();
        part[tid] += v;
        __syncthreads();
    }
    int ex = part[tid] - s;
    for (int i = 0; i < CH; i++) {
        int idx = base + i;
        if (idx < N_NODES) {
            g_off[idx] = ex;
            g_cur[idx] = ex;
            ex += g_cnt[idx];
        }
    }
    if (tid == 1023) g_off[N_NODES] = part[1023];
}

// ---------------- CSR fill ----------------------------------------------------
__global__ void fill_kernel(const void* __restrict__ ei,
                            const float* __restrict__ ew) {
    int e = blockIdx.x * blockDim.x + threadIdx.x;
    if (e >= N_EDGES) return;
    int is64 = g_is64;
    int s = edge_at(ei, e, is64);
    int d = edge_at(ei, (size_t)N_EDGES + e, is64);
    float w = g_dis[s] * ew[e] * g_dis[d];
    int pos = atomicAdd(&g_cur[d], 1);
    g_csr_src[pos] = s;
    g_csr_w[pos] = w;
}

// ---------------- propagation 1: CSR gather + bias + relu --------------------
__global__ __launch_bounds__(224)
void prop1_kernel(const float* __restrict__ b1) {
    const int n = blockIdx.x;
    const int col = threadIdx.x;
    if (col >= HID) return;
    float dv = g_dis[n];
    float acc = g_H1[(size_t)n * HID + col] * (dv * dv);
    int e = g_off[n], end = g_off[n + 1];
    for (; e + 4 <= end; e += 4) {
        int s0 = g_csr_src[e],     s1 = g_csr_src[e + 1];
        int s2 = g_csr_src[e + 2], s3 = g_csr_src[e + 3];
        float w0 = g_csr_w[e],     w1 = g_csr_w[e + 1];
        float w2 = g_csr_w[e + 2], w3 = g_csr_w[e + 3];
        float x0 = g_H1[(size_t)s0 * HID + col];
        float x1 = g_H1[(size_t)s1 * HID + col];
        float x2 = g_H1[(size_t)s2 * HID + col];
        float x3 = g_H1[(size_t)s3 * HID + col];
        acc += x0 * w0 + x1 * w1 + x2 * w2 + x3 * w3;
    }
    for (; e < end; e++)
        acc += g_H1[(size_t)g_csr_src[e] * HID + col] * g_csr_w[e];
    float v = acc + b1[col];
    g_h[(size_t)n * HID + col] = v > 0.f ? v : 0.f;
}

// ---------------- GEMM2 -------------------------------------------------------
__global__ void gemm2_kernel(const float* __restrict__ W2) {
    __shared__ float W2s[HID * OUT_DIM];
    int tid = threadIdx.x;
    for (int i = tid; i < HID * OUT_DIM; i += blockDim.x) W2s[i] = W2[i];
    __syncthreads();
    int row = blockIdx.x * blockDim.x + tid;
    if (row >= N_NODES) return;
    float acc[OUT_DIM];
#pragma unroll
    for (int o = 0; o < OUT_DIM; o++) acc[o] = 0.f;
    const float4* hq = reinterpret_cast<const float4*>(g_h + (size_t)row * HID);
#pragma unroll 5
    for (int q = 0; q < HID / 4; q++) {
        float4 v = hq[q];
        float hv[4] = {v.x, v.y, v.z, v.w};
#pragma unroll
        for (int j = 0; j < 4; j++) {
            int k = q * 4 + j;
#pragma unroll
            for (int o = 0; o < OUT_DIM; o++) acc[o] += hv[j] * W2s[k * OUT_DIM + o];
        }
    }
#pragma unroll
    for (int o = 0; o < OUT_DIM; o++)
        g_H2[(size_t)row * OUT_DIM + o] = acc[o];
}

// ---------------- propagation 2 ----------------------------------------------
__global__ void prop2_kernel(const float* __restrict__ b2,
                             float* __restrict__ outp) {
    int n = blockIdx.x * 4 + (threadIdx.x >> 5);
    if (n >= N_NODES) return;
    int lane = threadIdx.x & 31;
    int sub = lane >> 3;
    int col = lane & 7;
    float acc = 0.f;
    int beg = g_off[n], end = g_off[n + 1];
    for (int e = beg + sub; e < end; e += 4)
        acc += g_H2[(size_t)g_csr_src[e] * OUT_DIM + col] * g_csr_w[e];
    acc += __shfl_xor_sync(0xffffffffu, acc, 8);
    acc += __shfl_xor_sync(0xffffffffu, acc, 16);
    if (sub == 0) {
        float dv = g_dis[n];
        outp[(size_t)n * OUT_DIM + col] =
            acc + g_H2[(size_t)n * OUT_DIM + col] * (dv * dv) + b2[col];
    }
}

// ---------------- launch -----------------------------------------------------
extern "C" void kernel_launch(void* const* d_in, const int* in_sizes, int n_in,
                              void* d_out, int out_size) {
    const float* x  = (const float*)d_in[0];
    const float* ew = (const float*)d_in[1];
    const float* W1 = (const float*)d_in[2];
    const float* b1 = (const float*)d_in[3];
    const float* W2 = (const float*)d_in[4];
    const float* b2 = (const float*)d_in[5];
    const void*  ei = d_in[6];
    float* outp = (float*)d_out;

    static cudaStream_t s1 = nullptr;
    static cudaEvent_t evFork = nullptr, evJoin = nullptr;
    if (!s1) {
        cudaStreamCreateWithFlags(&s1, cudaStreamNonBlocking);
        cudaEventCreateWithFlags(&evFork, cudaEventDisableTiming);
        cudaEventCreateWithFlags(&evJoin, cudaEventDisableTiming);
    }

    cudaEventRecord(evFork, 0);
    cudaStreamWaitEvent(s1, evFork, 0);

    detect_kernel<<<1, 256, 0, s1>>>((const unsigned*)ei, 4096);
    init_kernel<<<(N_NODES + 255) / 256, 256, 0, s1>>>();
    w1t_kernel<<<dim3((HID + 31) / 32, (IN_DIM + 31) / 32), dim3(32, 8)>>>(W1);
    gemm1_kernel<<<(N_NODES + G1_BM - 1) / G1_BM, G1T>>>(x);
    accum_kernel<<<(N_EDGES + 255) / 256, 256, 0, s1>>>(ei, ew);
    rsqrt_kernel<<<(N_NODES + 255) / 256, 256, 0, s1>>>();
    scan_kernel<<<1, 1024, 0, s1>>>();
    fill_kernel<<<(N_EDGES + 255) / 256, 256, 0, s1>>>(ei, ew);

    cudaEventRecord(evJoin, s1);
    cudaStreamWaitEvent(0, evJoin, 0);

    prop1_kernel<<<N_NODES, 224>>>(b1);
    gemm2_kernel<<<(N_NODES + 255) / 256, 256>>>(W2);
    prop2_kernel<<<(N_NODES + 3) / 4, 128>>>(b2, outp);
}